// round 1
// baseline (speedup 1.0000x reference)
#include <cuda_runtime.h>
#include <math.h>

#define N_NODES 20000
#define N_EDGES 640000
#define FDIM 6
#define D 128
#define D4 512
#define STEPS 11   // 1 + DEPTH

// ----------------------------------------------------------------------------
// Scratch (device globals; no allocation anywhere)
// ----------------------------------------------------------------------------
__device__ float g_x0[N_NODES * 256];        // cols [0,128): agg(feat), cols [128,256): feat (= previous h2)
__device__ float g_h[3][N_NODES * D];
__device__ float g_c[3][N_NODES * D];
__device__ float g_gates[N_NODES * D4];
__device__ float g_bias[3 * D4];             // bih + bhh
__device__ int   g_deg[N_NODES];
__device__ int   g_rowstart[N_NODES + 1];
__device__ int   g_cursor[N_NODES];
__device__ int   g_csr[N_EDGES];

// ----------------------------------------------------------------------------
// Init / graph preprocessing
// ----------------------------------------------------------------------------
__global__ void zero_all_kernel() {
    int idx = blockIdx.x * blockDim.x + threadIdx.x;
    const int HC = 3 * N_NODES * D;
    if (idx < HC) {
        (&g_h[0][0])[idx] = 0.0f;
        (&g_c[0][0])[idx] = 0.0f;
    }
    if (idx < N_NODES) {
        g_deg[idx] = 0;
        g_cursor[idx] = 0;
    }
}

__global__ void bias_combine_kernel(const float* __restrict__ bih,
                                    const float* __restrict__ bhh) {
    int i = blockIdx.x * blockDim.x + threadIdx.x;
    if (i < 3 * D4) g_bias[i] = bih[i] + bhh[i];
}

// feat = relu(features @ W_in + b_in), written into the feat half of g_x0
__global__ void init_feat_kernel(const float* __restrict__ features,
                                 const float* __restrict__ W_in,
                                 const float* __restrict__ b_in) {
    __shared__ float sW[FDIM * D];
    __shared__ float sb[D];
    int t = threadIdx.x;
    for (int i = t; i < FDIM * D; i += blockDim.x) sW[i] = W_in[i];
    for (int i = t; i < D; i += blockDim.x) sb[i] = b_in[i];
    __syncthreads();
    int idx = blockIdx.x * blockDim.x + t;
    if (idx >= N_NODES * D) return;
    int n = idx >> 7;
    int d = idx & (D - 1);
    float acc = sb[d];
#pragma unroll
    for (int f = 0; f < FDIM; f++) acc += features[n * FDIM + f] * sW[f * D + d];
    g_x0[n * 256 + 128 + d] = fmaxf(acc, 0.0f);
}

__global__ void count_deg_kernel(const int* __restrict__ dst) {
    int e = blockIdx.x * blockDim.x + threadIdx.x;
    if (e < N_EDGES) atomicAdd(&g_deg[dst[e]], 1);
}

// Exclusive prefix sum of g_deg -> g_rowstart (single block, 1024 threads)
__global__ void scan_deg_kernel() {
    __shared__ int sh[1024];
    int t = threadIdx.x;
    int carry = 0;
    for (int base = 0; base < N_NODES; base += 1024) {
        int v = (base + t < N_NODES) ? g_deg[base + t] : 0;
        sh[t] = v;
        __syncthreads();
        for (int off = 1; off < 1024; off <<= 1) {
            int x = (t >= off) ? sh[t - off] : 0;
            __syncthreads();
            sh[t] += x;
            __syncthreads();
        }
        if (base + t < N_NODES) g_rowstart[base + t] = carry + sh[t] - v;
        int blocktotal = sh[1023];
        __syncthreads();
        carry += blocktotal;
    }
    if (t == 0) g_rowstart[N_NODES] = carry;
}

__global__ void fill_csr_kernel(const int* __restrict__ src,
                                const int* __restrict__ dst) {
    int e = blockIdx.x * blockDim.x + threadIdx.x;
    if (e < N_EDGES) {
        int d = dst[e];
        int pos = atomicAdd(&g_cursor[d], 1);
        g_csr[g_rowstart[d] + pos] = src[e];
    }
}

// ----------------------------------------------------------------------------
// Mean aggregation over incoming edges: one warp per node, float4 per lane
// reads feat half of g_x0, writes agg half of g_x0
// ----------------------------------------------------------------------------
__global__ void agg_kernel() {
    int warp = (blockIdx.x * blockDim.x + threadIdx.x) >> 5;
    int lane = threadIdx.x & 31;
    if (warp >= N_NODES) return;
    int s0 = g_rowstart[warp];
    int s1 = g_rowstart[warp + 1];
    float4 acc = make_float4(0.f, 0.f, 0.f, 0.f);
    for (int e = s0; e < s1; e++) {
        int s = g_csr[e];
        float4 v = *reinterpret_cast<const float4*>(&g_x0[s * 256 + 128 + lane * 4]);
        acc.x += v.x; acc.y += v.y; acc.z += v.z; acc.w += v.w;
    }
    float inv = (s1 > s0) ? 1.0f / (float)(s1 - s0) : 0.0f;
    acc.x *= inv; acc.y *= inv; acc.z *= inv; acc.w *= inv;
    *reinterpret_cast<float4*>(&g_x0[warp * 256 + lane * 4]) = acc;
}

// ----------------------------------------------------------------------------
// gates[N,512] = A1 @ W1^T + A2 @ W2^T + bias(layer)
// A1/A2 row-major [N, K], W row-major [512, K]
// BM=128, BN=64, BK=16, 256 threads, 8x4 per-thread tile
// ----------------------------------------------------------------------------
__global__ __launch_bounds__(256)
void gemm_gates_kernel(int layer,
                       const float* __restrict__ W1,
                       const float* __restrict__ W2) {
    const int BM = 128, BN = 64, BK = 16;
    __shared__ float As[BK][BM + 4];
    __shared__ float Bs[BK][BN + 4];

    const float* A1;
    int lda1, K1;
    if (layer == 0) { A1 = g_x0;           lda1 = 256; K1 = 256; }
    else            { A1 = g_h[layer - 1]; lda1 = D;   K1 = D;   }
    const float* A2 = g_h[layer];
    const int lda2 = D, K2 = D;
    const float* bias = g_bias + layer * D4;

    int tid = threadIdx.x;
    int tx = tid & 15;
    int ty = tid >> 4;
    int bm = blockIdx.x * BM;
    int bn = blockIdx.y * BN;

    float acc[8][4];
#pragma unroll
    for (int i = 0; i < 8; i++)
#pragma unroll
        for (int j = 0; j < 4; j++) acc[i][j] = 0.0f;

#pragma unroll 1
    for (int seg = 0; seg < 2; seg++) {
        const float* A = seg ? A2 : A1;
        const float* W = seg ? W2 : W1;
        int lda = seg ? lda2 : lda1;
        int K   = seg ? K2  : K1;
#pragma unroll 1
        for (int kb = 0; kb < K; kb += BK) {
            // Load A tile 128x16 (512 float4, 2 per thread), transpose to As[k][row]
#pragma unroll
            for (int l = 0; l < 2; l++) {
                int j = tid + l * 256;
                int row = j >> 2;
                int kk4 = (j & 3) * 4;
                float4 v = make_float4(0.f, 0.f, 0.f, 0.f);
                if (bm + row < N_NODES)
                    v = *reinterpret_cast<const float4*>(&A[(bm + row) * lda + kb + kk4]);
                As[kk4 + 0][row] = v.x;
                As[kk4 + 1][row] = v.y;
                As[kk4 + 2][row] = v.z;
                As[kk4 + 3][row] = v.w;
            }
            // Load W tile 64x16 (256 float4, 1 per thread), transpose to Bs[k][n]
            {
                int row = tid >> 2;
                int kk4 = (tid & 3) * 4;
                float4 v = *reinterpret_cast<const float4*>(&W[(bn + row) * K + kb + kk4]);
                Bs[kk4 + 0][row] = v.x;
                Bs[kk4 + 1][row] = v.y;
                Bs[kk4 + 2][row] = v.z;
                Bs[kk4 + 3][row] = v.w;
            }
            __syncthreads();
#pragma unroll
            for (int k = 0; k < BK; k++) {
                float4 a0 = *reinterpret_cast<const float4*>(&As[k][ty * 8]);
                float4 a1 = *reinterpret_cast<const float4*>(&As[k][ty * 8 + 4]);
                float4 b  = *reinterpret_cast<const float4*>(&Bs[k][tx * 4]);
                float av[8] = {a0.x, a0.y, a0.z, a0.w, a1.x, a1.y, a1.z, a1.w};
                float bv[4] = {b.x, b.y, b.z, b.w};
#pragma unroll
                for (int i = 0; i < 8; i++)
#pragma unroll
                    for (int j = 0; j < 4; j++)
                        acc[i][j] += av[i] * bv[j];
            }
            __syncthreads();
        }
    }

#pragma unroll
    for (int i = 0; i < 8; i++) {
        int r = bm + ty * 8 + i;
        if (r < N_NODES) {
#pragma unroll
            for (int j = 0; j < 4; j++)
                g_gates[r * D4 + bn + tx * 4 + j] = acc[i][j] + bias[bn + tx * 4 + j];
        }
    }
}

// ----------------------------------------------------------------------------
// LSTM cell elementwise: i,f,g,o gate order (PyTorch)
// ----------------------------------------------------------------------------
__device__ __forceinline__ float sigmoidf(float x) {
    return 1.0f / (1.0f + expf(-x));
}

__global__ void lstm_cell_kernel(int layer, int write_feat) {
    int idx = blockIdx.x * blockDim.x + threadIdx.x;
    if (idx >= N_NODES * D) return;
    int n = idx >> 7;
    int d = idx & (D - 1);
    const float* gr = g_gates + n * D4;
    float ig = sigmoidf(gr[d]);
    float fg = sigmoidf(gr[128 + d]);
    float gg = tanhf(gr[256 + d]);
    float og = sigmoidf(gr[384 + d]);
    float cn = fg * g_c[layer][idx] + ig * gg;
    g_c[layer][idx] = cn;
    float hn = og * tanhf(cn);
    g_h[layer][idx] = hn;
    if (write_feat) g_x0[n * 256 + 128 + d] = hn;   // feat for next step = h2
}

// ----------------------------------------------------------------------------
// out[n] = h2[n,:] . W_out + b_out
// ----------------------------------------------------------------------------
__global__ void out_kernel(const float* __restrict__ W_out,
                           const float* __restrict__ b_out,
                           float* __restrict__ out) {
    int warp = (blockIdx.x * blockDim.x + threadIdx.x) >> 5;
    int lane = threadIdx.x & 31;
    if (warp >= N_NODES) return;
    const float* h2 = &g_h[2][warp * D];
    float s = 0.0f;
#pragma unroll
    for (int i = 0; i < 4; i++) s += h2[lane + 32 * i] * W_out[lane + 32 * i];
#pragma unroll
    for (int off = 16; off; off >>= 1) s += __shfl_xor_sync(0xFFFFFFFFu, s, off);
    if (lane == 0) out[warp] = s + b_out[0];
}

// ----------------------------------------------------------------------------
// Launch
// ----------------------------------------------------------------------------
extern "C" void kernel_launch(void* const* d_in, const int* in_sizes, int n_in,
                              void* d_out, int out_size) {
    const float* features = (const float*)d_in[0];
    const int*   src      = (const int*)d_in[1];
    const int*   dst      = (const int*)d_in[2];
    const float* W_in     = (const float*)d_in[3];
    const float* b_in     = (const float*)d_in[4];
    const float* Wih0     = (const float*)d_in[5];
    const float* Wih_rest = (const float*)d_in[6];
    const float* Whh      = (const float*)d_in[7];
    const float* bih      = (const float*)d_in[8];
    const float* bhh      = (const float*)d_in[9];
    const float* W_out    = (const float*)d_in[10];
    const float* b_out    = (const float*)d_in[11];
    float* out = (float*)d_out;

    // init state + graph preprocessing
    {
        int tot = 3 * N_NODES * D;
        zero_all_kernel<<<(tot + 255) / 256, 256>>>();
    }
    bias_combine_kernel<<<(3 * D4 + 255) / 256, 256>>>(bih, bhh);
    init_feat_kernel<<<(N_NODES * D + 255) / 256, 256>>>(features, W_in, b_in);
    count_deg_kernel<<<(N_EDGES + 255) / 256, 256>>>(dst);
    scan_deg_kernel<<<1, 1024>>>();
    fill_csr_kernel<<<(N_EDGES + 255) / 256, 256>>>(src, dst);

    dim3 gemm_grid((N_NODES + 127) / 128, D4 / 64);
    int cell_blocks = (N_NODES * D + 255) / 256;
    int agg_blocks = (N_NODES * 32 + 255) / 256;

    const float* Wih1 = Wih_rest;
    const float* Wih2 = Wih_rest + D4 * D;
    const float* Whh0 = Whh;
    const float* Whh1 = Whh + D4 * D;
    const float* Whh2 = Whh + 2 * D4 * D;

    for (int s = 0; s < STEPS; s++) {
        agg_kernel<<<agg_blocks, 256>>>();
        // layer 0: x0 = [agg | feat] (K=256) + h0 (K=128)
        gemm_gates_kernel<<<gemm_grid, 256>>>(0, Wih0, Whh0);
        lstm_cell_kernel<<<cell_blocks, 256>>>(0, 0);
        // layer 1: h0 (K=128) + h1 (K=128)
        gemm_gates_kernel<<<gemm_grid, 256>>>(1, Wih1, Whh1);
        lstm_cell_kernel<<<cell_blocks, 256>>>(1, 0);
        // layer 2: h1 (K=128) + h2 (K=128); h2 becomes next-step feat
        gemm_gates_kernel<<<gemm_grid, 256>>>(2, Wih2, Whh2);
        lstm_cell_kernel<<<cell_blocks, 256>>>(2, 1);
    }

    out_kernel<<<(N_NODES * 32 + 255) / 256, 256>>>(W_out, b_out, out);
}

// round 3
// speedup vs baseline: 2.0031x; 2.0031x over previous
#include <cuda_runtime.h>
#include <cuda_fp16.h>
#include <math.h>
#include <stdint.h>

#define N_NODES 20000
#define N_EDGES 640000
#define FDIM 6
#define D 128
#define D4 512
#define STEPS 11          // 1 + DEPTH
#define K0 384            // layer0 K: agg(128)+feat(128)+h0(128)
#define K12 256           // layers 1,2 K: h_prev(128)+h_self(128)

#define BM 128
#define BN 64
#define BK 32

// ----------------------------------------------------------------------------
// Scratch (device globals; ping-pong parity buffers to avoid RW races)
// ----------------------------------------------------------------------------
__device__ float  g_A0[2][N_NODES * K0];    // [agg | feat | h0]
__device__ float  g_A1[2][N_NODES * K12];   // [h0 | h1]
__device__ float  g_A2[2][N_NODES * K12];   // [h1 | h2]
__device__ float  g_c[3][N_NODES * D];
__device__ __half g_W0[D4 * K0];            // interleaved-gate rows, fp16
__device__ __half g_W1[D4 * K12];
__device__ __half g_W2[D4 * K12];
__device__ float  g_bias_il[3 * D4];        // interleaved (bih+bhh)
__device__ int    g_deg[N_NODES];
__device__ int    g_rowstart[N_NODES + 1];
__device__ int    g_cursor[N_NODES];
__device__ int    g_csr[N_EDGES];

// ----------------------------------------------------------------------------
// Init / preprocessing
// ----------------------------------------------------------------------------
__global__ void zero_all_kernel() {
    int idx = blockIdx.x * blockDim.x + threadIdx.x;
    int stride = gridDim.x * blockDim.x;
    for (int i = idx; i < N_NODES * K0; i += stride)  g_A0[0][i] = 0.0f;
    for (int i = idx; i < N_NODES * K12; i += stride) g_A1[0][i] = 0.0f;
    for (int i = idx; i < N_NODES * K12; i += stride) g_A2[0][i] = 0.0f;
    for (int i = idx; i < 3 * N_NODES * D; i += stride) (&g_c[0][0])[i] = 0.0f;
    for (int i = idx; i < N_NODES; i += stride) { g_deg[i] = 0; g_cursor[i] = 0; }
}

// Build interleaved fp16 weights: row r = 4*d + g  <-  old row g*128+d,
// K = concat(Wih K-part, Whh 128)
__global__ void build_w_kernel(__half* dst, const float* __restrict__ Wih,
                               const float* __restrict__ Whh, int Kin) {
    int K = Kin + D;
    int idx = blockIdx.x * blockDim.x + threadIdx.x;
    if (idx >= D4 * K) return;
    int r = idx / K, k = idx % K;
    int d = r >> 2, g = r & 3;
    int orow = g * D + d;
    float v = (k < Kin) ? Wih[orow * Kin + k] : Whh[orow * D + (k - Kin)];
    dst[idx] = __float2half_rn(v);
}

__global__ void build_bias_kernel(const float* __restrict__ bih,
                                  const float* __restrict__ bhh) {
    int idx = blockIdx.x * blockDim.x + threadIdx.x;
    if (idx >= 3 * D4) return;
    int l = idx >> 9, r = idx & 511;
    int d = r >> 2, g = r & 3;
    int o = l * D4 + g * D + d;
    g_bias_il[idx] = bih[o] + bhh[o];
}

// feat = relu(features @ W_in + b_in)  -> g_A0[0] cols [128,256)
__global__ void init_feat_kernel(const float* __restrict__ features,
                                 const float* __restrict__ W_in,
                                 const float* __restrict__ b_in) {
    __shared__ float sW[FDIM * D];
    __shared__ float sb[D];
    int t = threadIdx.x;
    for (int i = t; i < FDIM * D; i += blockDim.x) sW[i] = W_in[i];
    for (int i = t; i < D; i += blockDim.x) sb[i] = b_in[i];
    __syncthreads();
    int idx = blockIdx.x * blockDim.x + t;
    if (idx >= N_NODES * D) return;
    int n = idx >> 7;
    int d = idx & (D - 1);
    float acc = sb[d];
#pragma unroll
    for (int f = 0; f < FDIM; f++) acc += features[n * FDIM + f] * sW[f * D + d];
    g_A0[0][n * K0 + D + d] = fmaxf(acc, 0.0f);
}

__global__ void count_deg_kernel(const int* __restrict__ dst) {
    int e = blockIdx.x * blockDim.x + threadIdx.x;
    if (e < N_EDGES) atomicAdd(&g_deg[dst[e]], 1);
}

__global__ void scan_deg_kernel() {
    __shared__ int sh[1024];
    int t = threadIdx.x;
    int carry = 0;
    for (int base = 0; base < N_NODES; base += 1024) {
        int v = (base + t < N_NODES) ? g_deg[base + t] : 0;
        sh[t] = v;
        __syncthreads();
        for (int off = 1; off < 1024; off <<= 1) {
            int x = (t >= off) ? sh[t - off] : 0;
            __syncthreads();
            sh[t] += x;
            __syncthreads();
        }
        if (base + t < N_NODES) g_rowstart[base + t] = carry + sh[t] - v;
        int blocktotal = sh[1023];
        __syncthreads();
        carry += blocktotal;
    }
    if (t == 0) g_rowstart[N_NODES] = carry;
}

__global__ void fill_csr_kernel(const int* __restrict__ src,
                                const int* __restrict__ dst) {
    int e = blockIdx.x * blockDim.x + threadIdx.x;
    if (e < N_EDGES) {
        int d = dst[e];
        int pos = atomicAdd(&g_cursor[d], 1);
        g_csr[g_rowstart[d] + pos] = src[e];
    }
}

// ----------------------------------------------------------------------------
// Mean aggregation: one warp per node, float4 per lane.
// Reads feat (A0[p] cols 128..255), writes agg (A0[p] cols 0..127).
// Disjoint column ranges -> no race.
// ----------------------------------------------------------------------------
__global__ void agg_kernel(const float* __restrict__ A0r, float* __restrict__ A0w) {
    int warp = (blockIdx.x * blockDim.x + threadIdx.x) >> 5;
    int lane = threadIdx.x & 31;
    if (warp >= N_NODES) return;
    int s0 = g_rowstart[warp];
    int s1 = g_rowstart[warp + 1];
    float4 acc = make_float4(0.f, 0.f, 0.f, 0.f);
    for (int e = s0; e < s1; e++) {
        int s = g_csr[e];
        float4 v = *reinterpret_cast<const float4*>(&A0r[s * K0 + D + lane * 4]);
        acc.x += v.x; acc.y += v.y; acc.z += v.z; acc.w += v.w;
    }
    float inv = (s1 > s0) ? 1.0f / (float)(s1 - s0) : 0.0f;
    acc.x *= inv; acc.y *= inv; acc.z *= inv; acc.w *= inv;
    *reinterpret_cast<float4*>(&A0w[warp * K0 + lane * 4]) = acc;
}

// ----------------------------------------------------------------------------
// Fused GEMM (fp16 tensor core) + LSTM cell epilogue
// gates[N, 512(il)] = A @ W^T + bias_il; then i,f,g,o -> c,h updates.
// h is written ONLY to buffers this kernel never reads (race-free).
// ----------------------------------------------------------------------------
struct SmemMM {
    __align__(16) __half A[BM][BK + 8];
    __align__(16) __half B[BN][BK + 8];
};
union SmemU {
    SmemMM mm;
    float C[BM][BN + 4];
};

__device__ __forceinline__ float sigmoidf_(float x) { return 1.0f / (1.0f + expf(-x)); }

__device__ __forceinline__ void ldmatrix_x4(uint32_t& r0, uint32_t& r1,
                                            uint32_t& r2, uint32_t& r3,
                                            const __half* p) {
    uint32_t addr = (uint32_t)__cvta_generic_to_shared(p);
    asm volatile("ldmatrix.sync.aligned.m8n8.x4.shared.b16 {%0,%1,%2,%3}, [%4];"
                 : "=r"(r0), "=r"(r1), "=r"(r2), "=r"(r3) : "r"(addr));
}

__global__ __launch_bounds__(256, 2)
void gemm_lstm_kernel(const float* __restrict__ Aop, int K,
                      const __half* __restrict__ W,
                      const float* __restrict__ bias,
                      float* __restrict__ cbuf,
                      float* __restrict__ hOut1, int s1,
                      float* __restrict__ hOut2, int s2) {
    __shared__ SmemU sm;

    int tid = threadIdx.x;
    int lane = tid & 31, warp = tid >> 5;
    int wr = warp >> 1, wc = warp & 1;          // warp grid 4(m) x 2(n)
    int bm = blockIdx.x * BM, bn = blockIdx.y * BN;

    float acc[2][4][4];
#pragma unroll
    for (int i = 0; i < 2; i++)
#pragma unroll
        for (int j = 0; j < 4; j++)
#pragma unroll
            for (int v = 0; v < 4; v++) acc[i][j][v] = 0.0f;

    int lmat_m = lane & 7;
    int lmat_id = lane >> 3;

#pragma unroll 1
    for (int kb = 0; kb < K; kb += BK) {
        // ---- load A tile [128 x 32] fp32 -> fp16 smem ----
#pragma unroll
        for (int l = 0; l < 4; l++) {
            int q = tid + l * 256;
            int row = q >> 3;
            int c4 = (q & 7) * 4;
            float4 v = make_float4(0.f, 0.f, 0.f, 0.f);
            if (bm + row < N_NODES)
                v = *reinterpret_cast<const float4*>(&Aop[(bm + row) * K + kb + c4]);
            __half2 p0 = __halves2half2(__float2half_rn(v.x), __float2half_rn(v.y));
            __half2 p1 = __halves2half2(__float2half_rn(v.z), __float2half_rn(v.w));
            *reinterpret_cast<__half2*>(&sm.mm.A[row][c4])     = p0;
            *reinterpret_cast<__half2*>(&sm.mm.A[row][c4 + 2]) = p1;
        }
        // ---- load B tile [64 x 32] fp16 ----
#pragma unroll
        for (int l = 0; l < 2; l++) {
            int q = tid + l * 256;
            int row = q >> 3;
            int c4 = (q & 7) * 4;
            uint2 v = *reinterpret_cast<const uint2*>(&W[(bn + row) * K + kb + c4]);
            *reinterpret_cast<uint2*>(&sm.mm.B[row][c4]) = v;
        }
        __syncthreads();

#pragma unroll
        for (int kk = 0; kk < BK; kk += 16) {
            uint32_t af[2][4];
            uint32_t bf[2][4];
#pragma unroll
            for (int i = 0; i < 2; i++) {
                int mrow = wr * 32 + i * 16 + (lmat_id & 1) * 8 + lmat_m;
                int kcol = kk + (lmat_id >> 1) * 8;
                ldmatrix_x4(af[i][0], af[i][1], af[i][2], af[i][3], &sm.mm.A[mrow][kcol]);
            }
#pragma unroll
            for (int jj = 0; jj < 2; jj++) {
                int nrow = wc * 32 + (jj * 2 + (lmat_id >> 1)) * 8 + lmat_m;
                int kcol = kk + (lmat_id & 1) * 8;
                ldmatrix_x4(bf[jj][0], bf[jj][1], bf[jj][2], bf[jj][3], &sm.mm.B[nrow][kcol]);
            }
#pragma unroll
            for (int i = 0; i < 2; i++)
#pragma unroll
                for (int j = 0; j < 4; j++) {
                    uint32_t b0 = bf[j >> 1][(j & 1) * 2 + 0];
                    uint32_t b1 = bf[j >> 1][(j & 1) * 2 + 1];
                    asm volatile(
                        "mma.sync.aligned.m16n8k16.row.col.f32.f16.f16.f32 "
                        "{%0,%1,%2,%3}, {%4,%5,%6,%7}, {%8,%9}, {%0,%1,%2,%3};"
                        : "+f"(acc[i][j][0]), "+f"(acc[i][j][1]),
                          "+f"(acc[i][j][2]), "+f"(acc[i][j][3])
                        : "r"(af[i][0]), "r"(af[i][1]), "r"(af[i][2]), "r"(af[i][3]),
                          "r"(b0), "r"(b1));
                }
        }
        __syncthreads();
    }

    // ---- stage C into smem (union reuse; all mm reads complete) ----
    int g = lane >> 2, t = lane & 3;
#pragma unroll
    for (int i = 0; i < 2; i++)
#pragma unroll
        for (int j = 0; j < 4; j++) {
            int row = wr * 32 + i * 16 + g;
            int col = wc * 32 + j * 8 + t * 2;
            *reinterpret_cast<float2*>(&sm.C[row][col]) =
                make_float2(acc[i][j][0], acc[i][j][1]);
            *reinterpret_cast<float2*>(&sm.C[row + 8][col]) =
                make_float2(acc[i][j][2], acc[i][j][3]);
        }
    __syncthreads();

    // ---- fused LSTM cell epilogue: 128 rows x 16 interleaved features ----
    int row = tid >> 1;
    int node = bm + row;
    if (node < N_NODES) {
        int f0 = (tid & 1) * 8;
#pragma unroll
        for (int fl = f0; fl < f0 + 8; fl++) {
            float4 gv = *reinterpret_cast<const float4*>(&sm.C[row][fl * 4]);
            float4 bb = *reinterpret_cast<const float4*>(&bias[bn + fl * 4]);
            float ig = sigmoidf_(gv.x + bb.x);
            float fg = sigmoidf_(gv.y + bb.y);
            float gg = tanhf(gv.z + bb.z);
            float og = sigmoidf_(gv.w + bb.w);
            int fglob = (bn >> 2) + fl;
            float cn = fg * cbuf[node * D + fglob] + ig * gg;
            cbuf[node * D + fglob] = cn;
            float hn = og * tanhf(cn);
            hOut1[node * s1 + fglob] = hn;
            hOut2[node * s2 + fglob] = hn;
        }
    }
}

// ----------------------------------------------------------------------------
// out[n] = h2[n,:] . W_out + b_out
// ----------------------------------------------------------------------------
__global__ void out_kernel(const float* __restrict__ h2base,
                           const float* __restrict__ W_out,
                           const float* __restrict__ b_out,
                           float* __restrict__ out) {
    int warp = (blockIdx.x * blockDim.x + threadIdx.x) >> 5;
    int lane = threadIdx.x & 31;
    if (warp >= N_NODES) return;
    const float* h2 = &h2base[warp * K12];
    float s = 0.0f;
#pragma unroll
    for (int i = 0; i < 4; i++) s += h2[lane + 32 * i] * W_out[lane + 32 * i];
#pragma unroll
    for (int off = 16; off; off >>= 1) s += __shfl_xor_sync(0xFFFFFFFFu, s, off);
    if (lane == 0) out[warp] = s + b_out[0];
}

// ----------------------------------------------------------------------------
// Launch
// ----------------------------------------------------------------------------
extern "C" void kernel_launch(void* const* d_in, const int* in_sizes, int n_in,
                              void* d_out, int out_size) {
    const float* features = (const float*)d_in[0];
    const int*   src      = (const int*)d_in[1];
    const int*   dst      = (const int*)d_in[2];
    const float* W_in     = (const float*)d_in[3];
    const float* b_in     = (const float*)d_in[4];
    const float* Wih0     = (const float*)d_in[5];
    const float* Wih_rest = (const float*)d_in[6];
    const float* Whh      = (const float*)d_in[7];
    const float* bih      = (const float*)d_in[8];
    const float* bhh      = (const float*)d_in[9];
    const float* W_out    = (const float*)d_in[10];
    const float* b_out    = (const float*)d_in[11];
    float* out = (float*)d_out;

    // Device-global base addresses (resolve via symbols on host is not allowed
    // in graph capture context, so compute via a tiny kernel-free trick:
    // we simply pass parity-selected pointers from device symbols' addresses.)
    static float *A0p[2] = {nullptr, nullptr}, *A1p[2], *A2p[2];
    static float *cp[3];
    static __half *W0p, *W1p, *W2p;
    static float *biasp;
    if (!A0p[0]) {
        cudaGetSymbolAddress((void**)&A0p[0], g_A0);
        A0p[1] = A0p[0] + N_NODES * K0;
        cudaGetSymbolAddress((void**)&A1p[0], g_A1);
        A1p[1] = A1p[0] + N_NODES * K12;
        cudaGetSymbolAddress((void**)&A2p[0], g_A2);
        A2p[1] = A2p[0] + N_NODES * K12;
        cudaGetSymbolAddress((void**)&cp[0], g_c);
        cp[1] = cp[0] + N_NODES * D;
        cp[2] = cp[1] + N_NODES * D;
        cudaGetSymbolAddress((void**)&W0p, g_W0);
        cudaGetSymbolAddress((void**)&W1p, g_W1);
        cudaGetSymbolAddress((void**)&W2p, g_W2);
        cudaGetSymbolAddress((void**)&biasp, g_bias_il);
    }

    zero_all_kernel<<<592, 256>>>();
    build_w_kernel<<<(D4 * K0 + 255) / 256, 256>>>(W0p, Wih0, Whh, 2 * D);
    build_w_kernel<<<(D4 * K12 + 255) / 256, 256>>>(W1p, Wih_rest, Whh + D4 * D, D);
    build_w_kernel<<<(D4 * K12 + 255) / 256, 256>>>(W2p, Wih_rest + D4 * D, Whh + 2 * D4 * D, D);
    build_bias_kernel<<<(3 * D4 + 255) / 256, 256>>>(bih, bhh);
    init_feat_kernel<<<(N_NODES * D + 255) / 256, 256>>>(features, W_in, b_in);
    count_deg_kernel<<<(N_EDGES + 255) / 256, 256>>>(dst);
    scan_deg_kernel<<<1, 1024>>>();
    fill_csr_kernel<<<(N_EDGES + 255) / 256, 256>>>(src, dst);

    dim3 gemm_grid((N_NODES + BM - 1) / BM, D4 / BN);   // 157 x 8
    int agg_blocks = (N_NODES * 32 + 255) / 256;

    for (int s = 0; s < STEPS; s++) {
        int p = s & 1, q = p ^ 1;
        agg_kernel<<<agg_blocks, 256>>>(A0p[p], A0p[p]);
        // layer0: reads A0[p]; writes h0 -> A1[p] cols[0,D) and A0[q] cols[2D,3D)
        gemm_lstm_kernel<<<gemm_grid, 256>>>(A0p[p], K0, W0p, biasp, cp[0],
                                             A1p[p], K12, A0p[q] + 2 * D, K0);
        // layer1: reads A1[p]; writes h1 -> A2[p] cols[0,D) and A1[q] cols[D,2D)
        gemm_lstm_kernel<<<gemm_grid, 256>>>(A1p[p], K12, W1p, biasp + D4, cp[1],
                                             A2p[p], K12, A1p[q] + D, K12);
        // layer2: reads A2[p]; writes h2 -> A2[q] cols[D,2D) and A0[q] cols[D,2D) (next feat)
        gemm_lstm_kernel<<<gemm_grid, 256>>>(A2p[p], K12, W2p, biasp + 2 * D4, cp[2],
                                             A2p[q] + D, K12, A0p[q] + D, K0);
    }

    // final h2 lives in A2[STEPS & 1] cols [D, 2D)
    out_kernel<<<(N_NODES * 32 + 255) / 256, 256>>>(A2p[STEPS & 1] + D, W_out, b_out, out);
}

// round 4
// speedup vs baseline: 2.4939x; 1.2450x over previous
#include <cuda_runtime.h>
#include <cuda_fp16.h>
#include <math.h>
#include <stdint.h>

#define N_NODES 20000
#define N_EDGES 640000
#define FDIM 6
#define D 128
#define D4 512
#define STEPS 11          // 1 + DEPTH
#define K0 384            // layer0 K: agg(128)+feat(128)+h0(128)
#define K12 256           // layers 1,2 K: h_prev(128)+h_self(128)

#define BM 128
#define BN 64
#define BK 64
#define LDA (BK + 8)              // 72 halfs: 144B row stride (16B multiple, conflict-free)
#define STAGE_HALFS ((BM + BN) * LDA)
#define SMEM_BYTES (2 * STAGE_HALFS * 2)   // 55296 > C staging 34816

// ----------------------------------------------------------------------------
// Scratch (device globals; ping-pong parity buffers; activations in fp16)
// ----------------------------------------------------------------------------
__device__ __half g_A0[2][N_NODES * K0];    // [agg | feat | h0]
__device__ __half g_A1[2][N_NODES * K12];   // [h0 | h1]
__device__ __half g_A2[2][N_NODES * K12];   // [h1 | h2]
__device__ float  g_c[3][N_NODES * D];
__device__ __half g_W0[D4 * K0];            // interleaved-gate rows, fp16
__device__ __half g_W1[D4 * K12];
__device__ __half g_W2[D4 * K12];
__device__ float  g_bias_il[3 * D4];        // interleaved (bih+bhh)
__device__ int    g_deg[N_NODES];
__device__ int    g_rowstart[N_NODES + 1];
__device__ int    g_cursor[N_NODES];
__device__ int    g_csr[N_EDGES];

// ----------------------------------------------------------------------------
// Init / preprocessing
// ----------------------------------------------------------------------------
__global__ void zero_all_kernel() {
    int idx = blockIdx.x * blockDim.x + threadIdx.x;
    int stride = gridDim.x * blockDim.x;
    // zero parity-0 activation buffers (as int words; element counts even)
    int* a0 = (int*)&g_A0[0][0];
    int* a1 = (int*)&g_A1[0][0];
    int* a2 = (int*)&g_A2[0][0];
    for (int i = idx; i < N_NODES * K0 / 2; i += stride)  a0[i] = 0;
    for (int i = idx; i < N_NODES * K12 / 2; i += stride) a1[i] = 0;
    for (int i = idx; i < N_NODES * K12 / 2; i += stride) a2[i] = 0;
    for (int i = idx; i < 3 * N_NODES * D; i += stride) (&g_c[0][0])[i] = 0.0f;
    for (int i = idx; i < N_NODES; i += stride) { g_deg[i] = 0; g_cursor[i] = 0; }
}

// Interleaved fp16 weights: row r = 4*d + g  <-  old row g*128+d; K = [Wih | Whh]
__global__ void build_w_kernel(__half* dst, const float* __restrict__ Wih,
                               const float* __restrict__ Whh, int Kin) {
    int K = Kin + D;
    int idx = blockIdx.x * blockDim.x + threadIdx.x;
    if (idx >= D4 * K) return;
    int r = idx / K, k = idx % K;
    int d = r >> 2, g = r & 3;
    int orow = g * D + d;
    float v = (k < Kin) ? Wih[orow * Kin + k] : Whh[orow * D + (k - Kin)];
    dst[idx] = __float2half_rn(v);
}

__global__ void build_bias_kernel(const float* __restrict__ bih,
                                  const float* __restrict__ bhh) {
    int idx = blockIdx.x * blockDim.x + threadIdx.x;
    if (idx >= 3 * D4) return;
    int l = idx >> 9, r = idx & 511;
    int d = r >> 2, g = r & 3;
    int o = l * D4 + g * D + d;
    g_bias_il[idx] = bih[o] + bhh[o];
}

// feat = relu(features @ W_in + b_in) -> g_A0[0] cols [128,256), fp16
__global__ void init_feat_kernel(const float* __restrict__ features,
                                 const float* __restrict__ W_in,
                                 const float* __restrict__ b_in) {
    __shared__ float sW[FDIM * D];
    __shared__ float sb[D];
    int t = threadIdx.x;
    for (int i = t; i < FDIM * D; i += blockDim.x) sW[i] = W_in[i];
    for (int i = t; i < D; i += blockDim.x) sb[i] = b_in[i];
    __syncthreads();
    int idx = blockIdx.x * blockDim.x + t;
    if (idx >= N_NODES * D) return;
    int n = idx >> 7;
    int d = idx & (D - 1);
    float acc = sb[d];
#pragma unroll
    for (int f = 0; f < FDIM; f++) acc += features[n * FDIM + f] * sW[f * D + d];
    g_A0[0][n * K0 + D + d] = __float2half_rn(fmaxf(acc, 0.0f));
}

__global__ void count_deg_kernel(const int* __restrict__ dst) {
    int e = blockIdx.x * blockDim.x + threadIdx.x;
    if (e < N_EDGES) atomicAdd(&g_deg[dst[e]], 1);
}

__global__ void scan_deg_kernel() {
    __shared__ int sh[1024];
    int t = threadIdx.x;
    int carry = 0;
    for (int base = 0; base < N_NODES; base += 1024) {
        int v = (base + t < N_NODES) ? g_deg[base + t] : 0;
        sh[t] = v;
        __syncthreads();
        for (int off = 1; off < 1024; off <<= 1) {
            int x = (t >= off) ? sh[t - off] : 0;
            __syncthreads();
            sh[t] += x;
            __syncthreads();
        }
        if (base + t < N_NODES) g_rowstart[base + t] = carry + sh[t] - v;
        int blocktotal = sh[1023];
        __syncthreads();
        carry += blocktotal;
    }
    if (t == 0) g_rowstart[N_NODES] = carry;
}

__global__ void fill_csr_kernel(const int* __restrict__ src,
                                const int* __restrict__ dst) {
    int e = blockIdx.x * blockDim.x + threadIdx.x;
    if (e < N_EDGES) {
        int d = dst[e];
        int pos = atomicAdd(&g_cursor[d], 1);
        g_csr[g_rowstart[d] + pos] = src[e];
    }
}

// ----------------------------------------------------------------------------
// Mean aggregation (fp16 in/out, fp32 accum): one warp per node, 4 halfs/lane
// ----------------------------------------------------------------------------
__global__ void agg_kernel(const __half* __restrict__ A0r, __half* __restrict__ A0w) {
    int warp = (blockIdx.x * blockDim.x + threadIdx.x) >> 5;
    int lane = threadIdx.x & 31;
    if (warp >= N_NODES) return;
    int s0 = g_rowstart[warp];
    int s1 = g_rowstart[warp + 1];
    float ax = 0.f, ay = 0.f, az = 0.f, aw = 0.f;
    for (int e = s0; e < s1; e++) {
        int s = g_csr[e];
        uint2 raw = *reinterpret_cast<const uint2*>(&A0r[s * K0 + D + lane * 4]);
        __half2 p0 = *reinterpret_cast<__half2*>(&raw.x);
        __half2 p1 = *reinterpret_cast<__half2*>(&raw.y);
        float2 f0 = __half22float2(p0);
        float2 f1 = __half22float2(p1);
        ax += f0.x; ay += f0.y; az += f1.x; aw += f1.y;
    }
    float inv = (s1 > s0) ? 1.0f / (float)(s1 - s0) : 0.0f;
    __half2 o0 = __floats2half2_rn(ax * inv, ay * inv);
    __half2 o1 = __floats2half2_rn(az * inv, aw * inv);
    uint2 outw;
    outw.x = *reinterpret_cast<uint32_t*>(&o0);
    outw.y = *reinterpret_cast<uint32_t*>(&o1);
    *reinterpret_cast<uint2*>(&A0w[warp * K0 + lane * 4]) = outw;
}

// ----------------------------------------------------------------------------
// Fused GEMM (fp16 mma, cp.async 2-stage pipeline) + LSTM cell epilogue
// ----------------------------------------------------------------------------
__device__ __forceinline__ float sigmoidf_(float x) { return 1.0f / (1.0f + expf(-x)); }

__device__ __forceinline__ void cp_async16(uint32_t saddr, const void* gaddr, int srcsize) {
    asm volatile("cp.async.cg.shared.global [%0], [%1], 16, %2;"
                 :: "r"(saddr), "l"(gaddr), "r"(srcsize));
}

__device__ __forceinline__ void ldmatrix_x4(uint32_t& r0, uint32_t& r1,
                                            uint32_t& r2, uint32_t& r3,
                                            uint32_t addr) {
    asm volatile("ldmatrix.sync.aligned.m8n8.x4.shared.b16 {%0,%1,%2,%3}, [%4];"
                 : "=r"(r0), "=r"(r1), "=r"(r2), "=r"(r3) : "r"(addr));
}

extern __shared__ __align__(16) char smem_raw[];

__global__ __launch_bounds__(256, 2)
void gemm_lstm_kernel(const __half* __restrict__ Aop, int K,
                      const __half* __restrict__ W,
                      const float* __restrict__ bias,
                      float* __restrict__ cbuf,
                      __half* __restrict__ hOut1, int s1,
                      __half* __restrict__ hOut2, int s2) {
    int tid = threadIdx.x;
    int lane = tid & 31, warp = tid >> 5;
    int wr = warp >> 1, wc = warp & 1;          // warp grid 4(m) x 2(n)
    int bm = blockIdx.x * BM, bn = blockIdx.y * BN;
    uint32_t smem_u32 = (uint32_t)__cvta_generic_to_shared(smem_raw);

    float acc[2][4][4];
#pragma unroll
    for (int i = 0; i < 2; i++)
#pragma unroll
        for (int j = 0; j < 4; j++)
#pragma unroll
            for (int v = 0; v < 4; v++) acc[i][j][v] = 0.0f;

    int lmat_m = lane & 7;
    int lmat_id = lane >> 3;
    int nk = K / BK;

    // stage issue: loads A[128xBK] + B[64xBK] for k-block `st` into buffer st&1
    auto issue = [&](int st) {
        int buf = st & 1;
        int kb = st * BK;
        uint32_t abase = smem_u32 + buf * STAGE_HALFS * 2;
        uint32_t bbase = abase + BM * LDA * 2;
#pragma unroll
        for (int l = 0; l < 4; l++) {
            int q = tid + l * 256;          // 0..1023 -> 128 rows x 8 chunks
            int row = q >> 3;
            int c8 = (q & 7) * 8;
            uint32_t saddr = abase + (row * LDA + c8) * 2;
            const __half* g = Aop + (size_t)(bm + row) * K + kb + c8;
            cp_async16(saddr, g, (bm + row < N_NODES) ? 16 : 0);
        }
#pragma unroll
        for (int l = 0; l < 2; l++) {
            int q = tid + l * 256;          // 0..511 -> 64 rows x 8 chunks
            int row = q >> 3;
            int c8 = (q & 7) * 8;
            uint32_t saddr = bbase + (row * LDA + c8) * 2;
            cp_async16(saddr, W + (size_t)(bn + row) * K + kb + c8, 16);
        }
        asm volatile("cp.async.commit_group;");
    };

    issue(0);
    issue(1);

#pragma unroll 1
    for (int i = 0; i < nk; i++) {
        if (i + 1 < nk) { asm volatile("cp.async.wait_group 1;"); }
        else            { asm volatile("cp.async.wait_group 0;"); }
        __syncthreads();

        int buf = i & 1;
        uint32_t abase = smem_u32 + buf * STAGE_HALFS * 2;
        uint32_t bbase = abase + BM * LDA * 2;
#pragma unroll
        for (int kk = 0; kk < BK; kk += 16) {
            uint32_t af[2][4];
            uint32_t bf[2][4];
#pragma unroll
            for (int ii = 0; ii < 2; ii++) {
                int mrow = wr * 32 + ii * 16 + (lmat_id & 1) * 8 + lmat_m;
                int kcol = kk + (lmat_id >> 1) * 8;
                ldmatrix_x4(af[ii][0], af[ii][1], af[ii][2], af[ii][3],
                            abase + (mrow * LDA + kcol) * 2);
            }
#pragma unroll
            for (int jj = 0; jj < 2; jj++) {
                int nrow = wc * 32 + (jj * 2 + (lmat_id >> 1)) * 8 + lmat_m;
                int kcol = kk + (lmat_id & 1) * 8;
                ldmatrix_x4(bf[jj][0], bf[jj][1], bf[jj][2], bf[jj][3],
                            bbase + (nrow * LDA + kcol) * 2);
            }
#pragma unroll
            for (int ii = 0; ii < 2; ii++)
#pragma unroll
                for (int j = 0; j < 4; j++) {
                    uint32_t b0 = bf[j >> 1][(j & 1) * 2 + 0];
                    uint32_t b1 = bf[j >> 1][(j & 1) * 2 + 1];
                    asm volatile(
                        "mma.sync.aligned.m16n8k16.row.col.f32.f16.f16.f32 "
                        "{%0,%1,%2,%3}, {%4,%5,%6,%7}, {%8,%9}, {%0,%1,%2,%3};"
                        : "+f"(acc[ii][j][0]), "+f"(acc[ii][j][1]),
                          "+f"(acc[ii][j][2]), "+f"(acc[ii][j][3])
                        : "r"(af[ii][0]), "r"(af[ii][1]), "r"(af[ii][2]), "r"(af[ii][3]),
                          "r"(b0), "r"(b1));
                }
        }
        __syncthreads();
        if (i + 2 < nk) issue(i + 2);
    }

    // ---- stage C into smem (reuse pipeline smem; all reads complete) ----
    float* Cs = (float*)smem_raw;           // [BM][BN+4]
    int g = lane >> 2, t = lane & 3;
#pragma unroll
    for (int i = 0; i < 2; i++)
#pragma unroll
        for (int j = 0; j < 4; j++) {
            int row = wr * 32 + i * 16 + g;
            int col = wc * 32 + j * 8 + t * 2;
            *reinterpret_cast<float2*>(&Cs[row * (BN + 4) + col]) =
                make_float2(acc[i][j][0], acc[i][j][1]);
            *reinterpret_cast<float2*>(&Cs[(row + 8) * (BN + 4) + col]) =
                make_float2(acc[i][j][2], acc[i][j][3]);
        }
    __syncthreads();

    // ---- fused LSTM cell epilogue: 2 threads per row, 8 features each ----
    int row = tid >> 1;
    int node = bm + row;
    if (node < N_NODES) {
        int f0 = (tid & 1) * 8;
        int fg0 = (bn >> 2) + f0;
        float4 c0 = *reinterpret_cast<float4*>(&cbuf[node * D + fg0]);
        float4 c1 = *reinterpret_cast<float4*>(&cbuf[node * D + fg0 + 4]);
        float* cv = &c0.x;                  // c0,c1 contiguous on stack? no — index explicitly
        __align__(16) __half hbuf[8];
#pragma unroll
        for (int tt = 0; tt < 8; tt++) {
            int fl = f0 + tt;
            float4 gv = *reinterpret_cast<const float4*>(&Cs[row * (BN + 4) + fl * 4]);
            float4 bb = *reinterpret_cast<const float4*>(&bias[bn + fl * 4]);
            float ig = sigmoidf_(gv.x + bb.x);
            float fg = sigmoidf_(gv.y + bb.y);
            float gg = tanhf(gv.z + bb.z);
            float og = sigmoidf_(gv.w + bb.w);
            float cprev;
            if (tt < 4) cprev = (tt == 0) ? c0.x : (tt == 1) ? c0.y : (tt == 2) ? c0.z : c0.w;
            else        cprev = (tt == 4) ? c1.x : (tt == 5) ? c1.y : (tt == 6) ? c1.z : c1.w;
            float cn = fg * cprev + ig * gg;
            if (tt < 4) { if (tt == 0) c0.x = cn; else if (tt == 1) c0.y = cn; else if (tt == 2) c0.z = cn; else c0.w = cn; }
            else        { if (tt == 4) c1.x = cn; else if (tt == 5) c1.y = cn; else if (tt == 6) c1.z = cn; else c1.w = cn; }
            hbuf[tt] = __float2half_rn(og * tanhf(cn));
        }
        (void)cv;
        *reinterpret_cast<float4*>(&cbuf[node * D + fg0]) = c0;
        *reinterpret_cast<float4*>(&cbuf[node * D + fg0 + 4]) = c1;
        uint4 hw = *reinterpret_cast<uint4*>(hbuf);
        *reinterpret_cast<uint4*>(&hOut1[node * s1 + fg0]) = hw;
        *reinterpret_cast<uint4*>(&hOut2[node * s2 + fg0]) = hw;
    }
}

// ----------------------------------------------------------------------------
// out[n] = h2[n,:] . W_out + b_out   (h2 fp16)
// ----------------------------------------------------------------------------
__global__ void out_kernel(const __half* __restrict__ h2base,
                           const float* __restrict__ W_out,
                           const float* __restrict__ b_out,
                           float* __restrict__ out) {
    int warp = (blockIdx.x * blockDim.x + threadIdx.x) >> 5;
    int lane = threadIdx.x & 31;
    if (warp >= N_NODES) return;
    const __half* h2 = &h2base[warp * K12];
    float s = 0.0f;
#pragma unroll
    for (int i = 0; i < 4; i++)
        s += __half2float(h2[lane + 32 * i]) * W_out[lane + 32 * i];
#pragma unroll
    for (int off = 16; off; off >>= 1) s += __shfl_xor_sync(0xFFFFFFFFu, s, off);
    if (lane == 0) out[warp] = s + b_out[0];
}

// ----------------------------------------------------------------------------
// Launch
// ----------------------------------------------------------------------------
extern "C" void kernel_launch(void* const* d_in, const int* in_sizes, int n_in,
                              void* d_out, int out_size) {
    const float* features = (const float*)d_in[0];
    const int*   src      = (const int*)d_in[1];
    const int*   dst      = (const int*)d_in[2];
    const float* W_in     = (const float*)d_in[3];
    const float* b_in     = (const float*)d_in[4];
    const float* Wih0     = (const float*)d_in[5];
    const float* Wih_rest = (const float*)d_in[6];
    const float* Whh      = (const float*)d_in[7];
    const float* bih      = (const float*)d_in[8];
    const float* bhh      = (const float*)d_in[9];
    const float* W_out    = (const float*)d_in[10];
    const float* b_out    = (const float*)d_in[11];
    float* out = (float*)d_out;

    static __half *A0p[2] = {nullptr, nullptr}, *A1p[2], *A2p[2];
    static float *cp[3];
    static __half *W0p, *W1p, *W2p;
    static float *biasp;
    if (!A0p[0]) {
        cudaGetSymbolAddress((void**)&A0p[0], g_A0);
        A0p[1] = A0p[0] + N_NODES * K0;
        cudaGetSymbolAddress((void**)&A1p[0], g_A1);
        A1p[1] = A1p[0] + N_NODES * K12;
        cudaGetSymbolAddress((void**)&A2p[0], g_A2);
        A2p[1] = A2p[0] + N_NODES * K12;
        cudaGetSymbolAddress((void**)&cp[0], g_c);
        cp[1] = cp[0] + N_NODES * D;
        cp[2] = cp[1] + N_NODES * D;
        cudaGetSymbolAddress((void**)&W0p, g_W0);
        cudaGetSymbolAddress((void**)&W1p, g_W1);
        cudaGetSymbolAddress((void**)&W2p, g_W2);
        cudaGetSymbolAddress((void**)&biasp, g_bias_il);
    }
    cudaFuncSetAttribute(gemm_lstm_kernel,
                         cudaFuncAttributeMaxDynamicSharedMemorySize, SMEM_BYTES);

    zero_all_kernel<<<592, 256>>>();
    build_w_kernel<<<(D4 * K0 + 255) / 256, 256>>>(W0p, Wih0, Whh, 2 * D);
    build_w_kernel<<<(D4 * K12 + 255) / 256, 256>>>(W1p, Wih_rest, Whh + D4 * D, D);
    build_w_kernel<<<(D4 * K12 + 255) / 256, 256>>>(W2p, Wih_rest + D4 * D, Whh + 2 * D4 * D, D);
    build_bias_kernel<<<(3 * D4 + 255) / 256, 256>>>(bih, bhh);
    init_feat_kernel<<<(N_NODES * D + 255) / 256, 256>>>(features, W_in, b_in);
    count_deg_kernel<<<(N_EDGES + 255) / 256, 256>>>(dst);
    scan_deg_kernel<<<1, 1024>>>();
    fill_csr_kernel<<<(N_EDGES + 255) / 256, 256>>>(src, dst);

    dim3 gemm_grid((N_NODES + BM - 1) / BM, D4 / BN);   // 157 x 8
    int agg_blocks = (N_NODES * 32 + 255) / 256;

    for (int s = 0; s < STEPS; s++) {
        int p = s & 1, q = p ^ 1;
        agg_kernel<<<agg_blocks, 256>>>(A0p[p], A0p[p]);
        // layer0: reads A0[p]; h0 -> A1[p][0,D) and A0[q][2D,3D)
        gemm_lstm_kernel<<<gemm_grid, 256, SMEM_BYTES>>>(A0p[p], K0, W0p, biasp, cp[0],
                                                         A1p[p], K12, A0p[q] + 2 * D, K0);
        // layer1: reads A1[p]; h1 -> A2[p][0,D) and A1[q][D,2D)
        gemm_lstm_kernel<<<gemm_grid, 256, SMEM_BYTES>>>(A1p[p], K12, W1p, biasp + D4, cp[1],
                                                         A2p[p], K12, A1p[q] + D, K12);
        // layer2: reads A2[p]; h2 -> A2[q][D,2D) and A0[q][D,2D) (next feat)
        gemm_lstm_kernel<<<gemm_grid, 256, SMEM_BYTES>>>(A2p[p], K12, W2p, biasp + 2 * D4, cp[2],
                                                         A2p[q] + D, K12, A0p[q] + D, K0);
    }

    out_kernel<<<(N_NODES * 32 + 255) / 256, 256>>>(A2p[STEPS & 1] + D, W_out, b_out, out);
}

// round 5
// speedup vs baseline: 3.7393x; 1.4994x over previous
#include <cuda_runtime.h>
#include <cuda_fp16.h>
#include <math.h>
#include <stdint.h>

#define N_NODES 20000
#define N_EDGES 640000
#define FDIM 6
#define D 128
#define D4 512
#define STEPS 11          // 1 + DEPTH
#define K0 384            // layer0 K: agg(128)+feat(128)+h0(128)
#define K12 256           // layers 1,2 K: h_prev(128)+h_self(128)

#define BM 128
#define BN 128
#define BK 64
#define NSTAGES 3
#define LDA (BK + 8)              // 72 halfs: 144B row stride (16B multiple)
#define STAGE_HALFS ((BM + BN) * LDA)
#define SMEM_BYTES (NSTAGES * STAGE_HALFS * 2)   // 110592 > C staging 67584

// ----------------------------------------------------------------------------
// Scratch (device globals; ping-pong parity buffers; activations in fp16)
// ----------------------------------------------------------------------------
__device__ __half g_A0[2][N_NODES * K0];    // [agg | feat | h0]
__device__ __half g_A1[2][N_NODES * K12];   // [h0 | h1]
__device__ __half g_A2[2][N_NODES * K12];   // [h1 | h2]
__device__ float  g_c[3][N_NODES * D];
__device__ __half g_W0[D4 * K0];            // interleaved-gate rows, fp16
__device__ __half g_W1[D4 * K12];
__device__ __half g_W2[D4 * K12];
__device__ float  g_bias_il[3 * D4];        // interleaved (bih+bhh)
__device__ int    g_deg[N_NODES];
__device__ int    g_rowstart[N_NODES + 1];
__device__ int    g_cursor[N_NODES];
__device__ int    g_csr[N_EDGES];

// ----------------------------------------------------------------------------
// Init / preprocessing
// ----------------------------------------------------------------------------
__global__ void zero_all_kernel() {
    int idx = blockIdx.x * blockDim.x + threadIdx.x;
    int stride = gridDim.x * blockDim.x;
    int* a0 = (int*)&g_A0[0][0];
    int* a1 = (int*)&g_A1[0][0];
    int* a2 = (int*)&g_A2[0][0];
    for (int i = idx; i < N_NODES * K0 / 2; i += stride)  a0[i] = 0;
    for (int i = idx; i < N_NODES * K12 / 2; i += stride) a1[i] = 0;
    for (int i = idx; i < N_NODES * K12 / 2; i += stride) a2[i] = 0;
    for (int i = idx; i < 3 * N_NODES * D; i += stride) (&g_c[0][0])[i] = 0.0f;
    for (int i = idx; i < N_NODES; i += stride) { g_deg[i] = 0; g_cursor[i] = 0; }
}

// Interleaved fp16 weights: row r = 4*d + g  <-  old row g*128+d; K = [Wih | Whh]
__global__ void build_w_kernel(__half* dst, const float* __restrict__ Wih,
                               const float* __restrict__ Whh, int Kin) {
    int K = Kin + D;
    int idx = blockIdx.x * blockDim.x + threadIdx.x;
    if (idx >= D4 * K) return;
    int r = idx / K, k = idx % K;
    int d = r >> 2, g = r & 3;
    int orow = g * D + d;
    float v = (k < Kin) ? Wih[orow * Kin + k] : Whh[orow * D + (k - Kin)];
    dst[idx] = __float2half_rn(v);
}

__global__ void build_bias_kernel(const float* __restrict__ bih,
                                  const float* __restrict__ bhh) {
    int idx = blockIdx.x * blockDim.x + threadIdx.x;
    if (idx >= 3 * D4) return;
    int l = idx >> 9, r = idx & 511;
    int d = r >> 2, g = r & 3;
    int o = l * D4 + g * D + d;
    g_bias_il[idx] = bih[o] + bhh[o];
}

// feat = relu(features @ W_in + b_in) -> g_A0[0] cols [128,256), fp16
__global__ void init_feat_kernel(const float* __restrict__ features,
                                 const float* __restrict__ W_in,
                                 const float* __restrict__ b_in) {
    __shared__ float sW[FDIM * D];
    __shared__ float sb[D];
    int t = threadIdx.x;
    for (int i = t; i < FDIM * D; i += blockDim.x) sW[i] = W_in[i];
    for (int i = t; i < D; i += blockDim.x) sb[i] = b_in[i];
    __syncthreads();
    int idx = blockIdx.x * blockDim.x + t;
    if (idx >= N_NODES * D) return;
    int n = idx >> 7;
    int d = idx & (D - 1);
    float acc = sb[d];
#pragma unroll
    for (int f = 0; f < FDIM; f++) acc += features[n * FDIM + f] * sW[f * D + d];
    g_A0[0][n * K0 + D + d] = __float2half_rn(fmaxf(acc, 0.0f));
}

__global__ void count_deg_kernel(const int* __restrict__ dst) {
    int e = blockIdx.x * blockDim.x + threadIdx.x;
    if (e < N_EDGES) atomicAdd(&g_deg[dst[e]], 1);
}

__global__ void scan_deg_kernel() {
    __shared__ int sh[1024];
    int t = threadIdx.x;
    int carry = 0;
    for (int base = 0; base < N_NODES; base += 1024) {
        int v = (base + t < N_NODES) ? g_deg[base + t] : 0;
        sh[t] = v;
        __syncthreads();
        for (int off = 1; off < 1024; off <<= 1) {
            int x = (t >= off) ? sh[t - off] : 0;
            __syncthreads();
            sh[t] += x;
            __syncthreads();
        }
        if (base + t < N_NODES) g_rowstart[base + t] = carry + sh[t] - v;
        int blocktotal = sh[1023];
        __syncthreads();
        carry += blocktotal;
    }
    if (t == 0) g_rowstart[N_NODES] = carry;
}

__global__ void fill_csr_kernel(const int* __restrict__ src,
                                const int* __restrict__ dst) {
    int e = blockIdx.x * blockDim.x + threadIdx.x;
    if (e < N_EDGES) {
        int d = dst[e];
        int pos = atomicAdd(&g_cursor[d], 1);
        g_csr[g_rowstart[d] + pos] = src[e];
    }
}

// ----------------------------------------------------------------------------
// Mean aggregation (fp16 in/out, fp32 accum): one warp per node, 4 halfs/lane
// ----------------------------------------------------------------------------
__global__ void agg_kernel(const __half* __restrict__ A0r, __half* __restrict__ A0w) {
    int warp = (blockIdx.x * blockDim.x + threadIdx.x) >> 5;
    int lane = threadIdx.x & 31;
    if (warp >= N_NODES) return;
    int s0 = g_rowstart[warp];
    int s1 = g_rowstart[warp + 1];
    float ax = 0.f, ay = 0.f, az = 0.f, aw = 0.f;
    for (int e = s0; e < s1; e++) {
        int s = g_csr[e];
        uint2 raw = *reinterpret_cast<const uint2*>(&A0r[s * K0 + D + lane * 4]);
        __half2 p0 = *reinterpret_cast<__half2*>(&raw.x);
        __half2 p1 = *reinterpret_cast<__half2*>(&raw.y);
        float2 f0 = __half22float2(p0);
        float2 f1 = __half22float2(p1);
        ax += f0.x; ay += f0.y; az += f1.x; aw += f1.y;
    }
    float inv = (s1 > s0) ? 1.0f / (float)(s1 - s0) : 0.0f;
    __half2 o0 = __floats2half2_rn(ax * inv, ay * inv);
    __half2 o1 = __floats2half2_rn(az * inv, aw * inv);
    uint2 outw;
    outw.x = *reinterpret_cast<uint32_t*>(&o0);
    outw.y = *reinterpret_cast<uint32_t*>(&o1);
    *reinterpret_cast<uint2*>(&A0w[warp * K0 + lane * 4]) = outw;
}

// ----------------------------------------------------------------------------
// Fused GEMM (fp16 mma, 3-stage cp.async pipeline) + LSTM cell epilogue
// ----------------------------------------------------------------------------
__device__ __forceinline__ float sigmoidf_(float x) { return 1.0f / (1.0f + expf(-x)); }

__device__ __forceinline__ void cp_async16(uint32_t saddr, const void* gaddr, int srcsize) {
    asm volatile("cp.async.cg.shared.global [%0], [%1], 16, %2;"
                 :: "r"(saddr), "l"(gaddr), "r"(srcsize));
}

__device__ __forceinline__ void ldmatrix_x4(uint32_t& r0, uint32_t& r1,
                                            uint32_t& r2, uint32_t& r3,
                                            uint32_t addr) {
    asm volatile("ldmatrix.sync.aligned.m8n8.x4.shared.b16 {%0,%1,%2,%3}, [%4];"
                 : "=r"(r0), "=r"(r1), "=r"(r2), "=r"(r3) : "r"(addr));
}

extern __shared__ __align__(16) char smem_raw[];

__global__ __launch_bounds__(256, 2)
void gemm_lstm_kernel(const __half* __restrict__ Aop, int K,
                      const __half* __restrict__ W,
                      const float* __restrict__ bias,
                      float* __restrict__ cbuf,
                      __half* __restrict__ hOut1, int s1,
                      __half* __restrict__ hOut2, int s2) {
    int tid = threadIdx.x;
    int lane = tid & 31, warp = tid >> 5;
    int wr = warp >> 1, wc = warp & 1;          // warp grid 4(m) x 2(n)
    int bm = blockIdx.x * BM, bn = blockIdx.y * BN;
    uint32_t smem_u32 = (uint32_t)__cvta_generic_to_shared(smem_raw);

    float acc[2][8][4];
#pragma unroll
    for (int i = 0; i < 2; i++)
#pragma unroll
        for (int j = 0; j < 8; j++)
#pragma unroll
            for (int v = 0; v < 4; v++) acc[i][j][v] = 0.0f;

    int lmat_m = lane & 7;
    int lmat_id = lane >> 3;
    int nk = K / BK;

    // stage issue: A[128xBK] + B[128xBK] for k-block `st` into buffer st%3
    auto issue = [&](int st) {
        int buf = st % NSTAGES;
        int kb = st * BK;
        uint32_t abase = smem_u32 + buf * STAGE_HALFS * 2;
        uint32_t bbase = abase + BM * LDA * 2;
#pragma unroll
        for (int l = 0; l < 4; l++) {
            int q = tid + l * 256;          // 0..1023 -> 128 rows x 8 chunks
            int row = q >> 3;
            int c8 = (q & 7) * 8;
            uint32_t saddr = abase + (row * LDA + c8) * 2;
            const __half* g = Aop + (size_t)(bm + row) * K + kb + c8;
            cp_async16(saddr, g, (bm + row < N_NODES) ? 16 : 0);
        }
#pragma unroll
        for (int l = 0; l < 4; l++) {
            int q = tid + l * 256;          // 0..1023 -> 128 rows x 8 chunks
            int row = q >> 3;
            int c8 = (q & 7) * 8;
            uint32_t saddr = bbase + (row * LDA + c8) * 2;
            cp_async16(saddr, W + (size_t)(bn + row) * K + kb + c8, 16);
        }
        asm volatile("cp.async.commit_group;");
    };

    issue(0);
    issue(1);
    asm volatile("cp.async.wait_group 1;");
    __syncthreads();

#pragma unroll 1
    for (int i = 0; i < nk; i++) {
        bool more = (i + 2 < nk);
        if (more) issue(i + 2);

        int buf = i % NSTAGES;
        uint32_t abase = smem_u32 + buf * STAGE_HALFS * 2;
        uint32_t bbase = abase + BM * LDA * 2;
#pragma unroll
        for (int kk = 0; kk < BK; kk += 16) {
            uint32_t af[2][4];
            uint32_t bf[4][4];
#pragma unroll
            for (int ii = 0; ii < 2; ii++) {
                int mrow = wr * 32 + ii * 16 + (lmat_id & 1) * 8 + lmat_m;
                int kcol = kk + (lmat_id >> 1) * 8;
                ldmatrix_x4(af[ii][0], af[ii][1], af[ii][2], af[ii][3],
                            abase + (mrow * LDA + kcol) * 2);
            }
#pragma unroll
            for (int jj = 0; jj < 4; jj++) {
                int nrow = wc * 64 + (jj * 2 + (lmat_id >> 1)) * 8 + lmat_m;
                int kcol = kk + (lmat_id & 1) * 8;
                ldmatrix_x4(bf[jj][0], bf[jj][1], bf[jj][2], bf[jj][3],
                            bbase + (nrow * LDA + kcol) * 2);
            }
#pragma unroll
            for (int ii = 0; ii < 2; ii++)
#pragma unroll
                for (int j = 0; j < 8; j++) {
                    uint32_t b0 = bf[j >> 1][(j & 1) * 2 + 0];
                    uint32_t b1 = bf[j >> 1][(j & 1) * 2 + 1];
                    asm volatile(
                        "mma.sync.aligned.m16n8k16.row.col.f32.f16.f16.f32 "
                        "{%0,%1,%2,%3}, {%4,%5,%6,%7}, {%8,%9}, {%0,%1,%2,%3};"
                        : "+f"(acc[ii][j][0]), "+f"(acc[ii][j][1]),
                          "+f"(acc[ii][j][2]), "+f"(acc[ii][j][3])
                        : "r"(af[ii][0]), "r"(af[ii][1]), "r"(af[ii][2]), "r"(af[ii][3]),
                          "r"(b0), "r"(b1));
                }
        }
        if (more) { asm volatile("cp.async.wait_group 1;"); }
        else      { asm volatile("cp.async.wait_group 0;"); }
        __syncthreads();
    }

    // ---- stage C into smem (reuse pipeline smem; all reads complete) ----
    float* Cs = (float*)smem_raw;           // [BM][BN+4]
    int g = lane >> 2, t = lane & 3;
#pragma unroll
    for (int i = 0; i < 2; i++)
#pragma unroll
        for (int j = 0; j < 8; j++) {
            int row = wr * 32 + i * 16 + g;
            int col = wc * 64 + j * 8 + t * 2;
            *reinterpret_cast<float2*>(&Cs[row * (BN + 4) + col]) =
                make_float2(acc[i][j][0], acc[i][j][1]);
            *reinterpret_cast<float2*>(&Cs[(row + 8) * (BN + 4) + col]) =
                make_float2(acc[i][j][2], acc[i][j][3]);
        }
    __syncthreads();

    // ---- fused LSTM cell epilogue: 2 threads per row, 16 features each ----
    int row = tid >> 1;
    int node = bm + row;
    if (node < N_NODES) {
        int f0 = (tid & 1) * 16;
        int fg0 = (bn >> 2) + f0;
        float cvals[16];
#pragma unroll
        for (int q4 = 0; q4 < 4; q4++) {
            float4 cv = *reinterpret_cast<float4*>(&cbuf[node * D + fg0 + q4 * 4]);
            cvals[q4 * 4 + 0] = cv.x; cvals[q4 * 4 + 1] = cv.y;
            cvals[q4 * 4 + 2] = cv.z; cvals[q4 * 4 + 3] = cv.w;
        }
        __align__(16) __half hbuf[16];
#pragma unroll
        for (int tt = 0; tt < 16; tt++) {
            int fl = f0 + tt;
            float4 gv = *reinterpret_cast<const float4*>(&Cs[row * (BN + 4) + fl * 4]);
            float4 bb = *reinterpret_cast<const float4*>(&bias[bn + fl * 4]);
            float ig = sigmoidf_(gv.x + bb.x);
            float fg = sigmoidf_(gv.y + bb.y);
            float gg = tanhf(gv.z + bb.z);
            float og = sigmoidf_(gv.w + bb.w);
            float cn = fg * cvals[tt] + ig * gg;
            cvals[tt] = cn;
            hbuf[tt] = __float2half_rn(og * tanhf(cn));
        }
#pragma unroll
        for (int q4 = 0; q4 < 4; q4++) {
            *reinterpret_cast<float4*>(&cbuf[node * D + fg0 + q4 * 4]) =
                make_float4(cvals[q4 * 4 + 0], cvals[q4 * 4 + 1],
                            cvals[q4 * 4 + 2], cvals[q4 * 4 + 3]);
        }
        uint4* hw = reinterpret_cast<uint4*>(hbuf);
        *reinterpret_cast<uint4*>(&hOut1[node * s1 + fg0]) = hw[0];
        *reinterpret_cast<uint4*>(&hOut1[node * s1 + fg0 + 8]) = hw[1];
        *reinterpret_cast<uint4*>(&hOut2[node * s2 + fg0]) = hw[0];
        *reinterpret_cast<uint4*>(&hOut2[node * s2 + fg0 + 8]) = hw[1];
    }
}

// ----------------------------------------------------------------------------
// out[n] = h2[n,:] . W_out + b_out   (h2 fp16)
// ----------------------------------------------------------------------------
__global__ void out_kernel(const __half* __restrict__ h2base,
                           const float* __restrict__ W_out,
                           const float* __restrict__ b_out,
                           float* __restrict__ out) {
    int warp = (blockIdx.x * blockDim.x + threadIdx.x) >> 5;
    int lane = threadIdx.x & 31;
    if (warp >= N_NODES) return;
    const __half* h2 = &h2base[warp * K12];
    float s = 0.0f;
#pragma unroll
    for (int i = 0; i < 4; i++)
        s += __half2float(h2[lane + 32 * i]) * W_out[lane + 32 * i];
#pragma unroll
    for (int off = 16; off; off >>= 1) s += __shfl_xor_sync(0xFFFFFFFFu, s, off);
    if (lane == 0) out[warp] = s + b_out[0];
}

// ----------------------------------------------------------------------------
// Launch
// ----------------------------------------------------------------------------
extern "C" void kernel_launch(void* const* d_in, const int* in_sizes, int n_in,
                              void* d_out, int out_size) {
    const float* features = (const float*)d_in[0];
    const int*   src      = (const int*)d_in[1];
    const int*   dst      = (const int*)d_in[2];
    const float* W_in     = (const float*)d_in[3];
    const float* b_in     = (const float*)d_in[4];
    const float* Wih0     = (const float*)d_in[5];
    const float* Wih_rest = (const float*)d_in[6];
    const float* Whh      = (const float*)d_in[7];
    const float* bih      = (const float*)d_in[8];
    const float* bhh      = (const float*)d_in[9];
    const float* W_out    = (const float*)d_in[10];
    const float* b_out    = (const float*)d_in[11];
    float* out = (float*)d_out;

    static __half *A0p[2] = {nullptr, nullptr}, *A1p[2], *A2p[2];
    static float *cp[3];
    static __half *W0p, *W1p, *W2p;
    static float *biasp;
    if (!A0p[0]) {
        cudaGetSymbolAddress((void**)&A0p[0], g_A0);
        A0p[1] = A0p[0] + N_NODES * K0;
        cudaGetSymbolAddress((void**)&A1p[0], g_A1);
        A1p[1] = A1p[0] + N_NODES * K12;
        cudaGetSymbolAddress((void**)&A2p[0], g_A2);
        A2p[1] = A2p[0] + N_NODES * K12;
        cudaGetSymbolAddress((void**)&cp[0], g_c);
        cp[1] = cp[0] + N_NODES * D;
        cp[2] = cp[1] + N_NODES * D;
        cudaGetSymbolAddress((void**)&W0p, g_W0);
        cudaGetSymbolAddress((void**)&W1p, g_W1);
        cudaGetSymbolAddress((void**)&W2p, g_W2);
        cudaGetSymbolAddress((void**)&biasp, g_bias_il);
    }
    cudaFuncSetAttribute(gemm_lstm_kernel,
                         cudaFuncAttributeMaxDynamicSharedMemorySize, SMEM_BYTES);

    zero_all_kernel<<<592, 256>>>();
    build_w_kernel<<<(D4 * K0 + 255) / 256, 256>>>(W0p, Wih0, Whh, 2 * D);
    build_w_kernel<<<(D4 * K12 + 255) / 256, 256>>>(W1p, Wih_rest, Whh + D4 * D, D);
    build_w_kernel<<<(D4 * K12 + 255) / 256, 256>>>(W2p, Wih_rest + D4 * D, Whh + 2 * D4 * D, D);
    build_bias_kernel<<<(3 * D4 + 255) / 256, 256>>>(bih, bhh);
    init_feat_kernel<<<(N_NODES * D + 255) / 256, 256>>>(features, W_in, b_in);
    count_deg_kernel<<<(N_EDGES + 255) / 256, 256>>>(dst);
    scan_deg_kernel<<<1, 1024>>>();
    fill_csr_kernel<<<(N_EDGES + 255) / 256, 256>>>(src, dst);

    dim3 gemm_grid((N_NODES + BM - 1) / BM, D4 / BN);   // 157 x 4
    int agg_blocks = (N_NODES * 32 + 255) / 256;

    for (int s = 0; s < STEPS; s++) {
        int p = s & 1, q = p ^ 1;
        agg_kernel<<<agg_blocks, 256>>>(A0p[p], A0p[p]);
        // layer0: reads A0[p]; h0 -> A1[p][0,D) and A0[q][2D,3D)
        gemm_lstm_kernel<<<gemm_grid, 256, SMEM_BYTES>>>(A0p[p], K0, W0p, biasp, cp[0],
                                                         A1p[p], K12, A0p[q] + 2 * D, K0);
        // layer1: reads A1[p]; h1 -> A2[p][0,D) and A1[q][D,2D)
        gemm_lstm_kernel<<<gemm_grid, 256, SMEM_BYTES>>>(A1p[p], K12, W1p, biasp + D4, cp[1],
                                                         A2p[p], K12, A1p[q] + D, K12);
        // layer2: reads A2[p]; h2 -> A2[q][D,2D) and A0[q][D,2D) (next feat)
        gemm_lstm_kernel<<<gemm_grid, 256, SMEM_BYTES>>>(A2p[p], K12, W2p, biasp + 2 * D4, cp[2],
                                                         A2p[q] + D, K12, A0p[q] + D, K0);
    }

    out_kernel<<<(N_NODES * 32 + 255) / 256, 256>>>(A2p[STEPS & 1] + D, W_out, b_out, out);
}